// round 1
// baseline (speedup 1.0000x reference)
#include <cuda_runtime.h>
#include <math.h>

#define NBOX 4096
#define WORDS 128   // NBOX/32
#define MM 20
#define HH 16

// ---------------- device scratch (allowed: __device__ globals) ----------------
__device__ unsigned int  g_ord[NBOX];
__device__ int           g_perm[NBOX];
__device__ float         g_boxes7[NBOX * 7];
__device__ float4        g_bev4[NBOX];
__device__ int           g_lab[NBOX];
__device__ unsigned int  g_sup0[WORDS];
__device__ unsigned int  g_rows[NBOX * WORDS];        // 2 MB adjacency bitmap
__device__ unsigned short g_list[NBOX * 32];          // per-row compact lists (<=31 entries)
__device__ unsigned char g_deg8[NBOX];                // degree, clamped to 255 (>31 => bitmap path)

// ---------------- kernel 1: sort keys ----------------
// descending by (valid? score : -inf), ties by index ascending (stable argsort)
__global__ void k_keys(const float* __restrict__ scores) {
    int i = blockIdx.x * blockDim.x + threadIdx.x;
    if (i >= NBOX) return;
    float sc = scores[i];
    float f = (sc > 0.2f) ? sc : __int_as_float(0xff800000); // -inf
    unsigned b = __float_as_uint(f);
    unsigned u = (b & 0x80000000u) ? ~b : (b | 0x80000000u); // ascending order map
    g_ord[i] = ~u;                                            // ascending key == score descending
}

// ---------------- kernel 2: O(N^2) rank sort ----------------
__global__ void k_rank() {
    __shared__ unsigned sk[NBOX];
    int t = threadIdx.x;
    for (int k = t; k < NBOX; k += blockDim.x) sk[k] = g_ord[k];
    __syncthreads();
    int i = blockIdx.x * blockDim.x + t;
    unsigned ki = sk[i];
    int rank = 0;
#pragma unroll 8
    for (int j = 0; j < NBOX; j++) {
        unsigned kj = sk[j];
        rank += (kj < ki) || (kj == ki && j < i);
    }
    g_perm[rank] = i;
}

// ---------------- kernel 3: gather sorted data, compute BEV, prefill outputs ----------------
__global__ void k_prep(const float* __restrict__ pb, const float* __restrict__ ps,
                       const int* __restrict__ pl, float* __restrict__ out) {
    int s = blockIdx.x * blockDim.x + threadIdx.x;  // blockDim=128, grid=32
    int o = g_perm[s];
    float b0 = pb[o*9+0], b1 = pb[o*9+1], b2 = pb[o*9+2];
    float b3 = pb[o*9+3], b4 = pb[o*9+4], b5 = pb[o*9+5];
    float b6 = pb[o*9+6], b7 = pb[o*9+7], b8 = pb[o*9+8];
    g_boxes7[s*7+0] = b0; g_boxes7[s*7+1] = b1; g_boxes7[s*7+2] = b2;
    g_boxes7[s*7+3] = b3; g_boxes7[s*7+4] = b4; g_boxes7[s*7+5] = b5;
    g_boxes7[s*7+6] = b6;
    out[s*9+0] = b0; out[s*9+1] = b1; out[s*9+2] = b2;
    out[s*9+3] = b3; out[s*9+4] = b4; out[s*9+5] = b5;
    out[s*9+6] = b6; out[s*9+7] = b7; out[s*9+8] = b8;

    const float PI = 3.14159265358979323846f;
    float ang = b6 - floorf(b6 / PI + 0.5f) * PI;
    bool sw = fabsf(ang) >= 0.25f * PI;
    float dx = sw ? b4 : b3;
    float dy = sw ? b3 : b4;
    g_bev4[s] = make_float4(b0 - dx * 0.5f, b1 - dy * 0.5f, b0 + dx * 0.5f, b1 + dy * 0.5f);

    int lab = pl[o];
    g_lab[s] = lab;
    float sc = ps[o];
    out[NBOX*9  + s] = sc;            // scores (sorted)
    out[NBOX*10 + s] = (float)lab;    // labels (sorted, cast)
    out[NBOX*11 + s] = 0.0f;          // keep prefill

    unsigned inval = __ballot_sync(0xffffffffu, !(sc > 0.2f));
    if ((threadIdx.x & 31) == 0) g_sup0[s >> 5] = inval;
}

// ---------------- kernel 4: adjacency bitmap (j>=i, same label, IoU>0.3) ----------------
__global__ void __launch_bounds__(1024) k_adj() {
    __shared__ float4 sb[1024];
    __shared__ int    sl[1024];
    __shared__ float4 rb[32];
    __shared__ int    rl[32];
    int t = threadIdx.x;
    int R = blockIdx.x * 32;
    if (t < 32) { rb[t] = g_bev4[R + t]; rl[t] = g_lab[R + t]; }
    __syncthreads();
    int rloc = t >> 5;
    int r = R + rloc;
    int wl = t & 31;
    float4 a = rb[rloc];
    int la = rl[rloc];
    float aa = (a.z - a.x) * (a.w - a.y);
    for (int T = 0; T < 4; T++) {
        sb[t] = g_bev4[T * 1024 + t];
        sl[t] = g_lab[T * 1024 + t];
        __syncthreads();
        int w = T * 32 + wl;
        int jbase = w * 32;
        unsigned m = 0;
#pragma unroll 4
        for (int b = 0; b < 32; b++) {
            int j = jbase + b;
            int jj = wl * 32 + b;
            float4 bb = sb[jj];
            bool ok = (j >= r) && (sl[jj] == la);
            if (ok) {
                float xmin = fmaxf(a.x, bb.x), ymin = fmaxf(a.y, bb.y);
                float xmax = fminf(a.z, bb.z), ymax = fminf(a.w, bb.w);
                float inter = fmaxf(xmax - xmin, 0.f) * fmaxf(ymax - ymin, 0.f);
                float ab = (bb.z - bb.x) * (bb.w - bb.y);
                float iou = inter / fmaxf(aa + ab - inter, 1e-6f);
                ok = iou > 0.3f;
            }
            if (ok) m |= (1u << b);
        }
        g_rows[r * WORDS + w] = m;
        __syncthreads();
    }
}

// ---------------- kernel 5: compact candidate lists from bitmap ----------------
__global__ void __launch_bounds__(1024) k_lists() {
    int gwarp = (blockIdx.x * blockDim.x + threadIdx.x) >> 5;
    int lane = threadIdx.x & 31;
    if (gwarp >= NBOX) return;
    const unsigned* row = g_rows + gwarp * WORDS;
    uint4 v4 = ((const uint4*)row)[lane];  // lane owns words [4l, 4l+4)
    unsigned ws[4] = { v4.x, v4.y, v4.z, v4.w };
    int pc = __popc(ws[0]) + __popc(ws[1]) + __popc(ws[2]) + __popc(ws[3]);
    int incl = pc;
    for (int d = 1; d < 32; d <<= 1) {
        int n = __shfl_up_sync(0xffffffffu, incl, d);
        if (lane >= d) incl += n;
    }
    int total = __shfl_sync(0xffffffffu, incl, 31);
    int running = incl - pc;   // exclusive prefix (global bit rank, diag is rank 0)
#pragma unroll
    for (int q = 0; q < 4; q++) {
        unsigned v = ws[q];
        int base_j = (lane * 4 + q) * 32;
        while (v) {
            int b = __ffs(v) - 1; v &= v - 1;
            if (running > 0) {               // skip diagonal (rank 0)
                int idx = running - 1;
                if (idx < 31) g_list[gwarp * 32 + idx] = (unsigned short)(base_j + b);
            }
            running++;
        }
    }
    if (lane == 0) {
        int deg = total - 1;
        g_deg8[gwarp] = (unsigned char)(deg > 255 ? 255 : deg);
    }
}

// ---------------- kernel 6: sequential NMS-merge scan (single block) ----------------
__global__ void __launch_bounds__(128) k_scan(
    const float* __restrict__ w1, const float* __restrict__ b1,
    const float* __restrict__ w2, const float* __restrict__ b2,
    const float* __restrict__ w3, const float* __restrict__ b3,
    float* __restrict__ out) {
    __shared__ unsigned sup[WORDS];
    __shared__ unsigned ovw[WORDS];
    __shared__ int cand[20];
    __shared__ int s_count;
    __shared__ float ob[140];          // [20][7]
    __shared__ float h1[112], h2[112]; // [7][16]
    __shared__ float sw1[320], sw2[256], sw3[16], sb1[16], sb2[16];
    __shared__ float sb3;
    __shared__ unsigned int sdeg_u[NBOX / 4]; // 4096 bytes of degrees

    int t = threadIdx.x;
    if (t < WORDS) sup[t] = g_sup0[t];
    for (int k = t; k < 320; k += 128) sw1[k] = w1[k];
    for (int k = t; k < 256; k += 128) sw2[k] = w2[k];
    if (t < 16) { sw3[t] = w3[t]; sb1[t] = b1[t]; sb2[t] = b2[t]; }
    if (t == 0) sb3 = b3[0];
    for (int k = t; k < NBOX / 4; k += 128) sdeg_u[k] = ((const unsigned int*)g_deg8)[k];
    __syncthreads();

    const unsigned char* sdeg = (const unsigned char*)sdeg_u;
    float* outKeep = out + NBOX * 11;

    for (int i = 0; i < NBOX; i++) {
        if ((sup[i >> 5] >> (i & 31)) & 1u) continue;   // suppressed: prefilled output is correct

        // idle warp prefetches upcoming candidate lists (hides serial L2 latency)
        if (t >= 32 && t < 40) {
            int ii = i + 1 + (t - 32);
            if (ii < NBOX)
                asm volatile("prefetch.global.L1 [%0];" :: "l"(g_list + ii * 32));
        }

        int deg = sdeg[i];
        if (deg <= 31) {
            // ---- fast path: one warp over compact list ----
            if (t < 32) {
                int j = i; bool val = true;
                if (t > 0) {
                    val = (t - 1) < deg;
                    j = val ? (int)g_list[i * 32 + (t - 1)] : 0;
                    if (val) val = ((sup[j >> 5] >> (j & 31)) & 1u) == 0u;
                }
                unsigned m = __ballot_sync(0xffffffffu, val);
                if (val) {
                    int rank = __popc(m & ((1u << t) - 1u));
                    if (rank < 20) cand[rank] = j;
                    atomicOr(&sup[j >> 5], 1u << (j & 31));
                }
                if (t == 0) s_count = __popc(m);
            }
        } else {
            // ---- exact bitmap fallback (rare) ----
            int w0 = i >> 5;
            unsigned ov = (t >= w0) ? (g_rows[i * WORDS + t] & ~sup[t]) : 0u;
            ovw[t] = ov;
            __syncthreads();
            sup[t] |= ov;
            if (t < 32) {
                int base = 0;
#pragma unroll
                for (int q = 0; q < 4; q++) {
                    unsigned wv = ovw[q * 32 + t];
                    int pc = __popc(wv);
                    int incl = pc;
                    for (int d = 1; d < 32; d <<= 1) {
                        int n = __shfl_up_sync(0xffffffffu, incl, d);
                        if (t >= d) incl += n;
                    }
                    int start = base + incl - pc;
                    unsigned v = wv;
                    while (v && start < 20) {
                        int b = __ffs(v) - 1; v &= v - 1;
                        cand[start++] = (q * 32 + t) * 32 + b;
                    }
                    base += __shfl_sync(0xffffffffu, incl, 31);
                }
                if (t == 0) s_count = base;
            }
        }
        __syncthreads();

        int cnt = s_count;
        if (cnt > 1) {
            int mc = cnt < 20 ? cnt : 20;
            for (int e = t; e < 140; e += 128) {
                int m = e / 7, d = e - m * 7;
                ob[e] = (m < mc) ? g_boxes7[cand[m] * 7 + d] : 0.f;
            }
            __syncthreads();
            if (t < 112) {
                int r = t >> 4, c = t & 15;
                float s = sb1[c];
#pragma unroll
                for (int k = 0; k < MM; k++) s += ob[k * 7 + r] * sw1[k * HH + c];
                h1[t] = fmaxf(s, 0.f);
            }
            __syncthreads();
            if (t < 112) {
                int r = t >> 4, c = t & 15;
                float s = sb2[c];
#pragma unroll
                for (int k = 0; k < HH; k++) s += h1[(r << 4) + k] * sw2[k * HH + c];
                h2[t] = fmaxf(s, 0.f);
            }
            __syncthreads();
            if (t < 7) {
                float s = sb3;
#pragma unroll
                for (int k = 0; k < HH; k++) s += h2[(t << 4) + k] * sw3[k];
                if (t >= 3 && t < 6) s = fmaxf(s, 1e-5f);
                out[i * 9 + t] = s;
            }
        }
        if (t == 0) outKeep[i] = 1.0f;
        __syncthreads();
    }
}

// ---------------- launch ----------------
extern "C" void kernel_launch(void* const* d_in, const int* in_sizes, int n_in,
                              void* d_out, int out_size) {
    const float* pb = (const float*)d_in[0];
    const float* ps = (const float*)d_in[1];
    const int*   pl = (const int*)  d_in[2];
    const float* w1 = (const float*)d_in[3];
    const float* b1 = (const float*)d_in[4];
    const float* w2 = (const float*)d_in[5];
    const float* b2 = (const float*)d_in[6];
    const float* w3 = (const float*)d_in[7];
    const float* b3 = (const float*)d_in[8];
    float* out = (float*)d_out;

    k_keys <<<16, 256>>>(ps);
    k_rank <<<32, 128>>>();
    k_prep <<<32, 128>>>(pb, ps, pl, out);
    k_adj  <<<128, 1024>>>();
    k_lists<<<128, 1024>>>();
    k_scan <<<1, 128>>>(w1, b1, w2, b2, w3, b3, out);
}

// round 3
// speedup vs baseline: 2.0403x; 2.0403x over previous
#include <cuda_runtime.h>
#include <math.h>

#define NBOX 4096
#define WORDS 128   // NBOX/32
#define MM 20
#define HH 16

// ---------------- device scratch ----------------
__device__ int            g_perm[NBOX];
__device__ float          g_boxes7[NBOX * 7];
__device__ float4         g_bev4[NBOX];
__device__ int            g_lab[NBOX];
__device__ unsigned int   g_sup0[WORDS];
__device__ unsigned int   g_rows[NBOX * WORDS];        // adjacency bitmap (upper-tri valid)
__device__ unsigned short g_list[NBOX * 32];           // compact lists (<=31 entries)
__device__ unsigned char  g_deg8[NBOX];
__device__ int            g_tasks[NBOX * 24];          // [i, cnt, cand0..cand19, pad, pad]
__device__ int            g_nt;
__device__ unsigned int   g_keep[WORDS];

__device__ __forceinline__ unsigned sort_key(float sc) {
    float f = (sc > 0.2f) ? sc : __int_as_float(0xff800000); // -inf if invalid
    unsigned b = __float_as_uint(f);
    unsigned u = (b & 0x80000000u) ? ~b : (b | 0x80000000u);
    return ~u;   // ascending == score descending
}

// ---------------- kernel 1: O(N^2) rank sort (keys computed inline) ----------------
__global__ void k_rank(const float* __restrict__ scores) {
    __shared__ unsigned sk[NBOX];
    int t = threadIdx.x;
    for (int k = t; k < NBOX; k += blockDim.x) sk[k] = sort_key(scores[k]);
    __syncthreads();
    int i = blockIdx.x * blockDim.x + t;
    unsigned ki = sk[i];
    int rank = 0;
#pragma unroll 8
    for (int j = 0; j < NBOX; j++) {
        unsigned kj = sk[j];
        rank += (kj < ki) || (kj == ki && j < i);
    }
    g_perm[rank] = i;
}

// ---------------- kernel 2: gather, BEV, prefill outputs ----------------
__global__ void k_prep(const float* __restrict__ pb, const float* __restrict__ ps,
                       const int* __restrict__ pl, float* __restrict__ out) {
    int s = blockIdx.x * blockDim.x + threadIdx.x;
    int o = g_perm[s];
    float b0 = pb[o*9+0], b1 = pb[o*9+1], b2 = pb[o*9+2];
    float b3 = pb[o*9+3], b4 = pb[o*9+4], b5 = pb[o*9+5];
    float b6 = pb[o*9+6], b7 = pb[o*9+7], b8 = pb[o*9+8];
    g_boxes7[s*7+0] = b0; g_boxes7[s*7+1] = b1; g_boxes7[s*7+2] = b2;
    g_boxes7[s*7+3] = b3; g_boxes7[s*7+4] = b4; g_boxes7[s*7+5] = b5;
    g_boxes7[s*7+6] = b6;
    out[s*9+0] = b0; out[s*9+1] = b1; out[s*9+2] = b2;
    out[s*9+3] = b3; out[s*9+4] = b4; out[s*9+5] = b5;
    out[s*9+6] = b6; out[s*9+7] = b7; out[s*9+8] = b8;

    const float PI = 3.14159265358979323846f;
    float ang = b6 - floorf(b6 / PI + 0.5f) * PI;
    bool sw = fabsf(ang) >= 0.25f * PI;
    float dx = sw ? b4 : b3;
    float dy = sw ? b3 : b4;
    g_bev4[s] = make_float4(b0 - dx * 0.5f, b1 - dy * 0.5f, b0 + dx * 0.5f, b1 + dy * 0.5f);

    int lab = pl[o];
    g_lab[s] = lab;
    float sc = ps[o];
    out[NBOX*9  + s] = sc;
    out[NBOX*10 + s] = (float)lab;

    unsigned inval = __ballot_sync(0xffffffffu, !(sc > 0.2f));
    if ((threadIdx.x & 31) == 0) g_sup0[s >> 5] = inval;
}

// ---------------- kernel 3: adjacency bitmap (upper-triangular only) ----------------
__global__ void __launch_bounds__(1024) k_adj() {
    __shared__ float4 sb[1024];
    __shared__ int    sl[1024];
    __shared__ float  sa[1024];
    __shared__ float4 rb[32];
    __shared__ int    rl[32];
    int t = threadIdx.x;
    int R = blockIdx.x * 32;
    if (t < 32) { rb[t] = g_bev4[R + t]; rl[t] = g_lab[R + t]; }
    __syncthreads();
    int rloc = t >> 5;
    int r = R + rloc;
    int wl = t & 31;
    float4 a = rb[rloc];
    int la = rl[rloc];
    float aa = (a.z - a.x) * (a.w - a.y);
    int T0 = R >> 10;                 // tiles strictly below block's rows are skipped
    for (int T = T0; T < 4; T++) {
        float4 bb0 = g_bev4[T * 1024 + t];
        sb[t] = bb0;
        sl[t] = g_lab[T * 1024 + t];
        sa[t] = (bb0.z - bb0.x) * (bb0.w - bb0.y);
        __syncthreads();
        int w = T * 32 + wl;
        int jbase = w * 32;
        if (jbase + 31 < r) { g_rows[r * WORDS + w] = 0u; }
        else {
            unsigned m = 0;
#pragma unroll 4
            for (int b = 0; b < 32; b++) {
                int j = jbase + b;
                int jj = wl * 32 + b;
                float4 bb = sb[jj];
                bool ok = (j >= r) && (sl[jj] == la);
                if (ok) {
                    float xmin = fmaxf(a.x, bb.x), ymin = fmaxf(a.y, bb.y);
                    float xmax = fminf(a.z, bb.z), ymax = fminf(a.w, bb.w);
                    float inter = fmaxf(xmax - xmin, 0.f) * fmaxf(ymax - ymin, 0.f);
                    float iou = inter / fmaxf(aa + sa[jj] - inter, 1e-6f);
                    ok = iou > 0.3f;
                }
                if (ok) m |= (1u << b);
            }
            g_rows[r * WORDS + w] = m;
        }
        __syncthreads();
    }
}

// ---------------- kernel 4: compact candidate lists ----------------
__global__ void __launch_bounds__(1024) k_lists() {
    int gwarp = (blockIdx.x * blockDim.x + threadIdx.x) >> 5;
    int lane = threadIdx.x & 31;
    if (gwarp >= NBOX) return;
    const unsigned* row = g_rows + gwarp * WORDS;
    uint4 v4 = ((const uint4*)row)[lane];
    int w0 = gwarp >> 5;
    unsigned ws[4];
    ws[0] = (lane*4+0 >= w0) ? v4.x : 0u;
    ws[1] = (lane*4+1 >= w0) ? v4.y : 0u;
    ws[2] = (lane*4+2 >= w0) ? v4.z : 0u;
    ws[3] = (lane*4+3 >= w0) ? v4.w : 0u;
    int pc = __popc(ws[0]) + __popc(ws[1]) + __popc(ws[2]) + __popc(ws[3]);
    int incl = pc;
    for (int d = 1; d < 32; d <<= 1) {
        int n = __shfl_up_sync(0xffffffffu, incl, d);
        if (lane >= d) incl += n;
    }
    int total = __shfl_sync(0xffffffffu, incl, 31);
    int running = incl - pc;   // global bit rank; diag (bit i) is rank 0
#pragma unroll
    for (int q = 0; q < 4; q++) {
        unsigned v = ws[q];
        int base_j = (lane * 4 + q) * 32;
        while (v) {
            int b = __ffs(v) - 1; v &= v - 1;
            if (running > 0) {
                int idx = running - 1;
                if (idx < 31) g_list[gwarp * 32 + idx] = (unsigned short)(base_j + b);
            }
            running++;
        }
    }
    if (lane == 0) {
        int deg = total - 1;
        g_deg8[gwarp] = (unsigned char)(deg > 255 ? 255 : deg);
    }
}

// ---------------- kernel 5: suppression-only scan (ONE WARP) ----------------
__global__ void __launch_bounds__(32) k_scanA() {
    __shared__ unsigned sup[WORDS];
    __shared__ unsigned kp[WORDS];
    __shared__ unsigned sdeg_u[NBOX / 4];
    int lane = threadIdx.x;
    for (int k = lane; k < WORDS; k += 32) { sup[k] = g_sup0[k]; kp[k] = 0u; }
    for (int k = lane; k < NBOX / 4; k += 32) sdeg_u[k] = ((const unsigned*)g_deg8)[k];
    __syncwarp();
    const unsigned char* sdeg = (const unsigned char*)sdeg_u;

    asm volatile("prefetch.global.L1 [%0];" :: "l"(g_list + lane * 32));

    int nt = 0;
    for (int w = 0; w < WORDS; w++) {
        if (w + 1 < WORDS)
            asm volatile("prefetch.global.L1 [%0];" :: "l"(g_list + ((w + 1) * 32 + lane) * 32));
        unsigned rem = ~sup[w];
        while (rem) {
            int b = __ffs(rem) - 1;
            int i = w * 32 + b;
            int deg = sdeg[i];
            if (deg <= 31) {
                bool val = lane < deg;
                int j = 0;
                if (val) {
                    j = (int)g_list[i * 32 + lane];
                    val = ((sup[j >> 5] >> (j & 31)) & 1u) == 0u;
                }
                unsigned m = __ballot_sync(0xffffffffu, val);
                int cnt = __popc(m) + 1;
                if (val) atomicOr(&sup[j >> 5], 1u << (j & 31));
                if (cnt > 1) {
                    int base = nt * 24;
                    if (lane == 0) { g_tasks[base] = i; g_tasks[base + 1] = cnt; g_tasks[base + 2] = i; }
                    if (val) {
                        int rank = __popc(m & ((1u << lane) - 1u));
                        if (rank < 19) g_tasks[base + 3 + rank] = j;
                    }
                    nt++;
                }
            } else {
                // exact bitmap fallback (rare)
                uint4 rv = ((const uint4*)(g_rows + (size_t)i * WORDS))[lane];
                int w0 = i >> 5;
                unsigned r0 = (4*lane+0 >= w0) ? rv.x : 0u;
                unsigned r1 = (4*lane+1 >= w0) ? rv.y : 0u;
                unsigned r2 = (4*lane+2 >= w0) ? rv.z : 0u;
                unsigned r3 = (4*lane+3 >= w0) ? rv.w : 0u;
                unsigned s0 = sup[4*lane+0], s1 = sup[4*lane+1];
                unsigned s2 = sup[4*lane+2], s3 = sup[4*lane+3];
                unsigned n0 = r0 & ~s0, n1 = r1 & ~s1, n2 = r2 & ~s2, n3 = r3 & ~s3;
                sup[4*lane+0] = s0 | n0; sup[4*lane+1] = s1 | n1;
                sup[4*lane+2] = s2 | n2; sup[4*lane+3] = s3 | n3;
                int pc = __popc(n0) + __popc(n1) + __popc(n2) + __popc(n3);
                int incl = pc;
                for (int d = 1; d < 32; d <<= 1) {
                    int v = __shfl_up_sync(0xffffffffu, incl, d);
                    if (lane >= d) incl += v;
                }
                int cnt = __shfl_sync(0xffffffffu, incl, 31);   // includes diag i
                if (cnt > 1) {
                    int base = nt * 24;
                    if (lane == 0) { g_tasks[base] = i; g_tasks[base + 1] = cnt; }
                    int start = incl - pc;
                    unsigned nn[4] = { n0, n1, n2, n3 };
#pragma unroll
                    for (int q = 0; q < 4; q++) {
                        unsigned v = nn[q];
                        while (v && start < 20) {
                            int bb = __ffs(v) - 1; v &= v - 1;
                            g_tasks[base + 2 + start] = (4 * lane + q) * 32 + bb;
                            start++;
                        }
                    }
                    nt++;
                }
            }
            if (lane == 0) kp[w] |= 1u << b;
            __syncwarp();
            rem = ~sup[w] & (0xfffffffeu << b);
        }
    }
    if (lane == 0) g_nt = nt;
    __syncwarp();
    for (int k = lane; k < WORDS; k += 32) g_keep[k] = kp[k];
}

// ---------------- kernel 6: parallel merge MLP + keep flags ----------------
__global__ void __launch_bounds__(128) k_merge(
    const float* __restrict__ w1, const float* __restrict__ b1,
    const float* __restrict__ w2, const float* __restrict__ b2,
    const float* __restrict__ w3, const float* __restrict__ b3,
    float* __restrict__ out) {
    __shared__ float ob[140];
    __shared__ float h1[112], h2[112];
    __shared__ float sw1[320], sw2[256], sw3[16], sb1v[16], sb2v[16];
    __shared__ float sb3v;
    int t = threadIdx.x;

    // keep flags (first 32 blocks, one 128-chunk each)
    if (blockIdx.x < 32) {
        int s = blockIdx.x * 128 + t;
        out[NBOX * 11 + s] = ((g_keep[s >> 5] >> (s & 31)) & 1u) ? 1.0f : 0.0f;
    }

    for (int k = t; k < 320; k += 128) sw1[k] = w1[k];
    for (int k = t; k < 256; k += 128) sw2[k] = w2[k];
    if (t < 16) { sw3[t] = w3[t]; sb1v[t] = b1[t]; sb2v[t] = b2[t]; }
    if (t == 0) sb3v = b3[0];
    __syncthreads();
    int nt = g_nt;
    for (int task = blockIdx.x; task < nt; task += gridDim.x) {
        int base = task * 24;
        int i = g_tasks[base];
        int cnt = g_tasks[base + 1];
        int mc = cnt < 20 ? cnt : 20;
        for (int e = t; e < 140; e += 128) {            // FIX: strided (covers all 140)
            int m = e / 7, d = e - m * 7;
            ob[e] = (m < mc) ? g_boxes7[g_tasks[base + 2 + m] * 7 + d] : 0.f;
        }
        __syncthreads();
        if (t < 112) {
            int r = t >> 4, c = t & 15;
            float s = sb1v[c];
#pragma unroll
            for (int k = 0; k < MM; k++) s += ob[k * 7 + r] * sw1[k * HH + c];
            h1[t] = fmaxf(s, 0.f);
        }
        __syncthreads();
        if (t < 112) {
            int r = t >> 4, c = t & 15;
            float s = sb2v[c];
#pragma unroll
            for (int k = 0; k < HH; k++) s += h1[(r << 4) + k] * sw2[k * HH + c];
            h2[t] = fmaxf(s, 0.f);
        }
        __syncthreads();
        if (t < 7) {
            float s = sb3v;
#pragma unroll
            for (int k = 0; k < HH; k++) s += h2[(t << 4) + k] * sw3[k];
            if (t >= 3 && t < 6) s = fmaxf(s, 1e-5f);
            out[i * 9 + t] = s;
        }
        __syncthreads();
    }
}

// ---------------- launch ----------------
extern "C" void kernel_launch(void* const* d_in, const int* in_sizes, int n_in,
                              void* d_out, int out_size) {
    const float* pb = (const float*)d_in[0];
    const float* ps = (const float*)d_in[1];
    const int*   pl = (const int*)  d_in[2];
    const float* w1 = (const float*)d_in[3];
    const float* b1 = (const float*)d_in[4];
    const float* w2 = (const float*)d_in[5];
    const float* b2 = (const float*)d_in[6];
    const float* w3 = (const float*)d_in[7];
    const float* b3 = (const float*)d_in[8];
    float* out = (float*)d_out;

    k_rank  <<<32, 128>>>(ps);
    k_prep  <<<32, 128>>>(pb, ps, pl, out);
    k_adj   <<<128, 1024>>>();
    k_lists <<<128, 1024>>>();
    k_scanA <<<1, 32>>>();
    k_merge <<<256, 128>>>(w1, b1, w2, b2, w3, b3, out);
}

// round 4
// speedup vs baseline: 3.9244x; 1.9234x over previous
#include <cuda_runtime.h>
#include <math.h>

#define NBOX 4096
#define WORDS 128   // NBOX/32
#define MM 20
#define HH 16
#define NLAB 4      // labels actually in {0,1,2}; 4th warp idles

// ---------------- device scratch ----------------
__device__ int            g_perm[NBOX];
__device__ float          g_boxes7[NBOX * 7];
__device__ float4         g_bev4[NBOX];
__device__ int            g_lab[NBOX];
__device__ unsigned int   g_sup0[WORDS];
__device__ unsigned int   g_labmask[NLAB * WORDS];
__device__ unsigned int   g_rows[NBOX * WORDS];        // adjacency bitmap (upper-tri words >= w0 valid)
__device__ unsigned short g_list[NBOX * 32];           // compact lists (<=31 entries)
__device__ unsigned char  g_deg8[NBOX];
__device__ int            g_tasks[NLAB * NBOX * 24];   // per-label regions: [i, cnt, cand0..19, pad2]
__device__ int            g_ntv[NLAB];
__device__ unsigned int   g_keep[WORDS];

__device__ __forceinline__ unsigned sort_key(float sc) {
    float f = (sc > 0.2f) ? sc : __int_as_float(0xff800000); // -inf if invalid
    unsigned b = __float_as_uint(f);
    unsigned u = (b & 0x80000000u) ? ~b : (b | 0x80000000u);
    return ~u;   // ascending == score descending
}

// ---------------- kernel 1: O(N^2) rank sort ----------------
__global__ void k_rank(const float* __restrict__ scores) {
    __shared__ unsigned sk[NBOX];
    int t = threadIdx.x;
    for (int k = t; k < NBOX; k += blockDim.x) sk[k] = sort_key(scores[k]);
    __syncthreads();
    int i = blockIdx.x * blockDim.x + t;
    unsigned ki = sk[i];
    int rank = 0;
#pragma unroll 8
    for (int j = 0; j < NBOX; j++) {
        unsigned kj = sk[j];
        rank += (kj < ki) || (kj == ki && j < i);
    }
    g_perm[rank] = i;
}

// ---------------- kernel 2: gather, BEV, label masks, prefill outputs ----------------
__global__ void k_prep(const float* __restrict__ pb, const float* __restrict__ ps,
                       const int* __restrict__ pl, float* __restrict__ out) {
    int s = blockIdx.x * blockDim.x + threadIdx.x;
    int o = g_perm[s];
    float b0 = pb[o*9+0], b1 = pb[o*9+1], b2 = pb[o*9+2];
    float b3 = pb[o*9+3], b4 = pb[o*9+4], b5 = pb[o*9+5];
    float b6 = pb[o*9+6], b7 = pb[o*9+7], b8 = pb[o*9+8];
    g_boxes7[s*7+0] = b0; g_boxes7[s*7+1] = b1; g_boxes7[s*7+2] = b2;
    g_boxes7[s*7+3] = b3; g_boxes7[s*7+4] = b4; g_boxes7[s*7+5] = b5;
    g_boxes7[s*7+6] = b6;
    out[s*9+0] = b0; out[s*9+1] = b1; out[s*9+2] = b2;
    out[s*9+3] = b3; out[s*9+4] = b4; out[s*9+5] = b5;
    out[s*9+6] = b6; out[s*9+7] = b7; out[s*9+8] = b8;

    const float PI = 3.14159265358979323846f;
    float ang = b6 - floorf(b6 / PI + 0.5f) * PI;
    bool sw = fabsf(ang) >= 0.25f * PI;
    float dx = sw ? b4 : b3;
    float dy = sw ? b3 : b4;
    g_bev4[s] = make_float4(b0 - dx * 0.5f, b1 - dy * 0.5f, b0 + dx * 0.5f, b1 + dy * 0.5f);

    int lab = pl[o];
    g_lab[s] = lab;
    float sc = ps[o];
    out[NBOX*9  + s] = sc;
    out[NBOX*10 + s] = (float)lab;

    unsigned inval = __ballot_sync(0xffffffffu, !(sc > 0.2f));
    if ((threadIdx.x & 31) == 0) g_sup0[s >> 5] = inval;
#pragma unroll
    for (int L = 0; L < NLAB; L++) {
        unsigned lm = __ballot_sync(0xffffffffu, lab == L);
        if ((threadIdx.x & 31) == 0) g_labmask[L * WORDS + (s >> 5)] = lm;
    }
}

// ---------------- kernel 3: adjacency bitmap (upper-triangular only) ----------------
__global__ void __launch_bounds__(1024) k_adj() {
    __shared__ float4 sb[1024];
    __shared__ int    sl[1024];
    __shared__ float  sa[1024];
    __shared__ float4 rb[32];
    __shared__ int    rl[32];
    int t = threadIdx.x;
    int R = blockIdx.x * 32;
    if (t < 32) { rb[t] = g_bev4[R + t]; rl[t] = g_lab[R + t]; }
    __syncthreads();
    int rloc = t >> 5;
    int r = R + rloc;
    int wl = t & 31;
    float4 a = rb[rloc];
    int la = rl[rloc];
    float aa = (a.z - a.x) * (a.w - a.y);
    int T0 = R >> 10;
    for (int T = T0; T < 4; T++) {
        float4 bb0 = g_bev4[T * 1024 + t];
        sb[t] = bb0;
        sl[t] = g_lab[T * 1024 + t];
        sa[t] = (bb0.z - bb0.x) * (bb0.w - bb0.y);
        __syncthreads();
        int w = T * 32 + wl;
        int jbase = w * 32;
        if (jbase + 31 >= r) {                 // sub-diagonal words never read (readers mask)
            unsigned m = 0;
#pragma unroll 4
            for (int b = 0; b < 32; b++) {
                int j = jbase + b;
                int jj = wl * 32 + b;
                float4 bb = sb[jj];
                bool ok = (j >= r) && (sl[jj] == la);
                if (ok) {
                    float xmin = fmaxf(a.x, bb.x), ymin = fmaxf(a.y, bb.y);
                    float xmax = fminf(a.z, bb.z), ymax = fminf(a.w, bb.w);
                    float inter = fmaxf(xmax - xmin, 0.f) * fmaxf(ymax - ymin, 0.f);
                    float iou = inter / fmaxf(aa + sa[jj] - inter, 1e-6f);
                    ok = iou > 0.3f;
                }
                if (ok) m |= (1u << b);
            }
            g_rows[r * WORDS + w] = m;
        }
        __syncthreads();
    }
}

// ---------------- kernel 4: compact candidate lists ----------------
__global__ void __launch_bounds__(1024) k_lists() {
    int gwarp = (blockIdx.x * blockDim.x + threadIdx.x) >> 5;
    int lane = threadIdx.x & 31;
    if (gwarp >= NBOX) return;
    const unsigned* row = g_rows + gwarp * WORDS;
    uint4 v4 = ((const uint4*)row)[lane];
    int w0 = gwarp >> 5;
    unsigned ws[4];
    ws[0] = (lane*4+0 >= w0) ? v4.x : 0u;
    ws[1] = (lane*4+1 >= w0) ? v4.y : 0u;
    ws[2] = (lane*4+2 >= w0) ? v4.z : 0u;
    ws[3] = (lane*4+3 >= w0) ? v4.w : 0u;
    int pc = __popc(ws[0]) + __popc(ws[1]) + __popc(ws[2]) + __popc(ws[3]);
    int incl = pc;
    for (int d = 1; d < 32; d <<= 1) {
        int n = __shfl_up_sync(0xffffffffu, incl, d);
        if (lane >= d) incl += n;
    }
    int total = __shfl_sync(0xffffffffu, incl, 31);
    int running = incl - pc;   // global bit rank; diag (bit i) is rank 0
#pragma unroll
    for (int q = 0; q < 4; q++) {
        unsigned v = ws[q];
        int base_j = (lane * 4 + q) * 32;
        while (v) {
            int b = __ffs(v) - 1; v &= v - 1;
            if (running > 0) {
                int idx = running - 1;
                if (idx < 31) g_list[gwarp * 32 + idx] = (unsigned short)(base_j + b);
            }
            running++;
        }
    }
    if (lane == 0) {
        int deg = total - 1;
        g_deg8[gwarp] = (unsigned char)(deg > 255 ? 255 : deg);
    }
}

// ---------------- kernel 5: per-label parallel suppression scans (4 warps) ----------------
__global__ void __launch_bounds__(128) k_scanA() {
    __shared__ unsigned sup[WORDS];
    __shared__ unsigned kp[WORDS];
    __shared__ unsigned sdeg_u[NBOX / 4];
    int t = threadIdx.x;
    int L = t >> 5;              // warp = label
    int lane = t & 31;
    for (int k = t; k < WORDS; k += 128) { sup[k] = g_sup0[k]; kp[k] = 0u; }
    for (int k = t; k < NBOX / 4; k += 128) sdeg_u[k] = ((const unsigned*)g_deg8)[k];
    __syncthreads();
    const unsigned char* sdeg = (const unsigned char*)sdeg_u;
    const unsigned* labm = g_labmask + L * WORDS;

    asm volatile("prefetch.global.L1 [%0];" :: "l"(g_list + lane * 32));

    int nt = 0;
    for (int w = 0; w < WORDS; w++) {
        if (w + 1 < WORDS)
            asm volatile("prefetch.global.L1 [%0];" :: "l"(g_list + ((w + 1) * 32 + lane) * 32));
        unsigned lm = labm[w];
        if (!lm) continue;
        unsigned rem = ~sup[w] & lm;
        unsigned kpw = 0;
        while (rem) {
            int b = __ffs(rem) - 1;
            int i = w * 32 + b;
            kpw |= 1u << b;
            int deg = sdeg[i];
            if (deg <= 31) {
                bool val = lane < deg;
                int j = 0;
                if (val) {
                    j = (int)g_list[i * 32 + lane];
                    val = ((sup[j >> 5] >> (j & 31)) & 1u) == 0u;
                }
                unsigned m = __ballot_sync(0xffffffffu, val);
                int cnt = __popc(m) + 1;
                if (val) atomicOr(&sup[j >> 5], 1u << (j & 31));
                // newly-suppressed bits landing in the current word (no smem round-trip)
                unsigned self = (val && ((j >> 5) == w)) ? (1u << (j & 31)) : 0u;
                unsigned cur = __reduce_or_sync(0xffffffffu, self);
                if (cnt > 1) {
                    int base = (L * NBOX + nt) * 24;
                    if (lane == 0) { g_tasks[base] = i; g_tasks[base + 1] = cnt; g_tasks[base + 2] = i; }
                    if (val) {
                        int rank = __popc(m & ((1u << lane) - 1u));
                        if (rank < 19) g_tasks[base + 3 + rank] = j;
                    }
                    nt++;
                }
                rem &= ~cur & (0xfffffffeu << b);
            } else {
                // exact bitmap fallback (rare)
                uint4 rv = ((const uint4*)(g_rows + (size_t)i * WORDS))[lane];
                int w0 = i >> 5;
                unsigned r0 = (4*lane+0 >= w0) ? rv.x : 0u;
                unsigned r1 = (4*lane+1 >= w0) ? rv.y : 0u;
                unsigned r2 = (4*lane+2 >= w0) ? rv.z : 0u;
                unsigned r3 = (4*lane+3 >= w0) ? rv.w : 0u;
                // row bits are same-label only; other warps never touch them
                unsigned n0 = r0 & ~sup[4*lane+0], n1 = r1 & ~sup[4*lane+1];
                unsigned n2 = r2 & ~sup[4*lane+2], n3 = r3 & ~sup[4*lane+3];
                if (n0) atomicOr(&sup[4*lane+0], n0);
                if (n1) atomicOr(&sup[4*lane+1], n1);
                if (n2) atomicOr(&sup[4*lane+2], n2);
                if (n3) atomicOr(&sup[4*lane+3], n3);
                int pc = __popc(n0) + __popc(n1) + __popc(n2) + __popc(n3);
                int incl = pc;
                for (int d = 1; d < 32; d <<= 1) {
                    int v = __shfl_up_sync(0xffffffffu, incl, d);
                    if (lane >= d) incl += v;
                }
                int cnt = __shfl_sync(0xffffffffu, incl, 31);   // includes diag i
                if (cnt > 1) {
                    int base = (L * NBOX + nt) * 24;
                    if (lane == 0) { g_tasks[base] = i; g_tasks[base + 1] = cnt; }
                    int start = incl - pc;
                    unsigned nn[4] = { n0, n1, n2, n3 };
#pragma unroll
                    for (int q = 0; q < 4; q++) {
                        unsigned v = nn[q];
                        while (v && start < 20) {
                            int bb = __ffs(v) - 1; v &= v - 1;
                            g_tasks[base + 2 + start] = (4 * lane + q) * 32 + bb;
                            start++;
                        }
                    }
                    nt++;
                }
                // this word's newly suppressed bits (from owner lane)
                int oq = w & 3;
                unsigned nown = (oq == 0) ? n0 : (oq == 1) ? n1 : (oq == 2) ? n2 : n3;
                unsigned cur = __shfl_sync(0xffffffffu, nown, w >> 2);
                rem &= ~cur & (0xfffffffeu << b);
            }
            __syncwarp();
        }
        if (lane == 0 && kpw) atomicOr(&kp[w], kpw);
    }
    if (lane == 0) g_ntv[L] = nt;
    __syncthreads();
    for (int k = t; k < WORDS; k += 128) g_keep[k] = kp[k];
}

// ---------------- kernel 6: parallel merge MLP + keep flags ----------------
__global__ void __launch_bounds__(128) k_merge(
    const float* __restrict__ w1, const float* __restrict__ b1,
    const float* __restrict__ w2, const float* __restrict__ b2,
    const float* __restrict__ w3, const float* __restrict__ b3,
    float* __restrict__ out) {
    __shared__ float ob[140];
    __shared__ float h1[112], h2[112];
    __shared__ float sw1[320], sw2[256], sw3[16], sb1v[16], sb2v[16];
    __shared__ float sb3v;
    int t = threadIdx.x;

    if (blockIdx.x < 32) {
        int s = blockIdx.x * 128 + t;
        out[NBOX * 11 + s] = ((g_keep[s >> 5] >> (s & 31)) & 1u) ? 1.0f : 0.0f;
    }

    for (int k = t; k < 320; k += 128) sw1[k] = w1[k];
    for (int k = t; k < 256; k += 128) sw2[k] = w2[k];
    if (t < 16) { sw3[t] = w3[t]; sb1v[t] = b1[t]; sb2v[t] = b2[t]; }
    if (t == 0) sb3v = b3[0];
    __syncthreads();

    for (int L = 0; L < NLAB; L++) {
        int nt = g_ntv[L];
        for (int task = blockIdx.x; task < nt; task += gridDim.x) {
            int base = (L * NBOX + task) * 24;
            int i = g_tasks[base];
            int cnt = g_tasks[base + 1];
            int mc = cnt < 20 ? cnt : 20;
            for (int e = t; e < 140; e += 128) {
                int m = e / 7, d = e - m * 7;
                ob[e] = (m < mc) ? g_boxes7[g_tasks[base + 2 + m] * 7 + d] : 0.f;
            }
            __syncthreads();
            if (t < 112) {
                int r = t >> 4, c = t & 15;
                float s = sb1v[c];
#pragma unroll
                for (int k = 0; k < MM; k++) s += ob[k * 7 + r] * sw1[k * HH + c];
                h1[t] = fmaxf(s, 0.f);
            }
            __syncthreads();
            if (t < 112) {
                int r = t >> 4, c = t & 15;
                float s = sb2v[c];
#pragma unroll
                for (int k = 0; k < HH; k++) s += h1[(r << 4) + k] * sw2[k * HH + c];
                h2[t] = fmaxf(s, 0.f);
            }
            __syncthreads();
            if (t < 7) {
                float s = sb3v;
#pragma unroll
                for (int k = 0; k < HH; k++) s += h2[(t << 4) + k] * sw3[k];
                if (t >= 3 && t < 6) s = fmaxf(s, 1e-5f);
                out[i * 9 + t] = s;
            }
            __syncthreads();
        }
    }
}

// ---------------- launch ----------------
extern "C" void kernel_launch(void* const* d_in, const int* in_sizes, int n_in,
                              void* d_out, int out_size) {
    const float* pb = (const float*)d_in[0];
    const float* ps = (const float*)d_in[1];
    const int*   pl = (const int*)  d_in[2];
    const float* w1 = (const float*)d_in[3];
    const float* b1 = (const float*)d_in[4];
    const float* w2 = (const float*)d_in[5];
    const float* b2 = (const float*)d_in[6];
    const float* w3 = (const float*)d_in[7];
    const float* b3 = (const float*)d_in[8];
    float* out = (float*)d_out;

    k_rank  <<<32, 128>>>(ps);
    k_prep  <<<32, 128>>>(pb, ps, pl, out);
    k_adj   <<<128, 1024>>>();
    k_lists <<<128, 1024>>>();
    k_scanA <<<1, 128>>>();
    k_merge <<<256, 128>>>(w1, b1, w2, b2, w3, b3, out);
}

// round 5
// speedup vs baseline: 5.4083x; 1.3781x over previous
#include <cuda_runtime.h>
#include <math.h>

#define NBOX 4096
#define WORDS 128   // NBOX/32
#define MM 20
#define HH 16
#define NLAB 4      // labels actually in {0,1,2}; 4th warp idles

// ---------------- device scratch ----------------
__device__ int            g_perm[NBOX];
__device__ float          g_boxes7[NBOX * 7];
__device__ float4         g_bev4[NBOX];
__device__ int            g_lab[NBOX];
__device__ unsigned int   g_sup0[WORDS];
__device__ unsigned int   g_labmask[NLAB * WORDS];
__device__ unsigned int   g_rows[NBOX * WORDS];        // adjacency bitmap (words >= w0 valid)
__device__ unsigned short g_list[NBOX * 32];           // compact lists (<=31 entries)
__device__ unsigned char  g_deg8[NBOX];
__device__ int            g_tasks[NLAB * NBOX * 24];   // per-label regions: [i, cnt, cand0..19, pad2]
__device__ int            g_ntv[NLAB];
__device__ unsigned int   g_keep[WORDS];

__device__ __forceinline__ unsigned sort_key(float sc) {
    float f = (sc > 0.2f) ? sc : __int_as_float(0xff800000); // -inf if invalid
    unsigned b = __float_as_uint(f);
    unsigned u = (b & 0x80000000u) ? ~b : (b | 0x80000000u);
    return ~u;   // ascending == score descending
}

// ---------------- kernel 1: O(N^2) rank sort ----------------
__global__ void k_rank(const float* __restrict__ scores) {
    __shared__ unsigned sk[NBOX];
    int t = threadIdx.x;
    for (int k = t; k < NBOX; k += blockDim.x) sk[k] = sort_key(scores[k]);
    __syncthreads();
    int i = blockIdx.x * blockDim.x + t;
    unsigned ki = sk[i];
    int rank = 0;
#pragma unroll 8
    for (int j = 0; j < NBOX; j++) {
        unsigned kj = sk[j];
        rank += (kj < ki) || (kj == ki && j < i);
    }
    g_perm[rank] = i;
}

// ---------------- kernel 2: gather, BEV, label masks, prefill outputs ----------------
__global__ void k_prep(const float* __restrict__ pb, const float* __restrict__ ps,
                       const int* __restrict__ pl, float* __restrict__ out) {
    int s = blockIdx.x * blockDim.x + threadIdx.x;
    int o = g_perm[s];
    float b0 = pb[o*9+0], b1 = pb[o*9+1], b2 = pb[o*9+2];
    float b3 = pb[o*9+3], b4 = pb[o*9+4], b5 = pb[o*9+5];
    float b6 = pb[o*9+6], b7 = pb[o*9+7], b8 = pb[o*9+8];
    g_boxes7[s*7+0] = b0; g_boxes7[s*7+1] = b1; g_boxes7[s*7+2] = b2;
    g_boxes7[s*7+3] = b3; g_boxes7[s*7+4] = b4; g_boxes7[s*7+5] = b5;
    g_boxes7[s*7+6] = b6;
    out[s*9+0] = b0; out[s*9+1] = b1; out[s*9+2] = b2;
    out[s*9+3] = b3; out[s*9+4] = b4; out[s*9+5] = b5;
    out[s*9+6] = b6; out[s*9+7] = b7; out[s*9+8] = b8;

    const float PI = 3.14159265358979323846f;
    float ang = b6 - floorf(b6 / PI + 0.5f) * PI;
    bool sw = fabsf(ang) >= 0.25f * PI;
    float dx = sw ? b4 : b3;
    float dy = sw ? b3 : b4;
    g_bev4[s] = make_float4(b0 - dx * 0.5f, b1 - dy * 0.5f, b0 + dx * 0.5f, b1 + dy * 0.5f);

    int lab = pl[o];
    g_lab[s] = lab;
    float sc = ps[o];
    out[NBOX*9  + s] = sc;
    out[NBOX*10 + s] = (float)lab;

    unsigned inval = __ballot_sync(0xffffffffu, !(sc > 0.2f));
    if ((threadIdx.x & 31) == 0) g_sup0[s >> 5] = inval;
#pragma unroll
    for (int L = 0; L < NLAB; L++) {
        unsigned lm = __ballot_sync(0xffffffffu, lab == L);
        if ((threadIdx.x & 31) == 0) g_labmask[L * WORDS + (s >> 5)] = lm;
    }
}

// ---------------- kernel 3: adjacency bitmap (upper-triangular only) ----------------
__global__ void __launch_bounds__(1024) k_adj() {
    __shared__ float4 sb[1024];
    __shared__ int    sl[1024];
    __shared__ float  sa[1024];
    __shared__ float4 rb[32];
    __shared__ int    rl[32];
    int t = threadIdx.x;
    int R = blockIdx.x * 32;
    if (t < 32) { rb[t] = g_bev4[R + t]; rl[t] = g_lab[R + t]; }
    __syncthreads();
    int rloc = t >> 5;
    int r = R + rloc;
    int wl = t & 31;
    float4 a = rb[rloc];
    int la = rl[rloc];
    float aa = (a.z - a.x) * (a.w - a.y);
    int T0 = R >> 10;
    for (int T = T0; T < 4; T++) {
        float4 bb0 = g_bev4[T * 1024 + t];
        sb[t] = bb0;
        sl[t] = g_lab[T * 1024 + t];
        sa[t] = (bb0.z - bb0.x) * (bb0.w - bb0.y);
        __syncthreads();
        int w = T * 32 + wl;
        int jbase = w * 32;
        if (jbase + 31 >= r) {
            unsigned m = 0;
#pragma unroll 4
            for (int b = 0; b < 32; b++) {
                int j = jbase + b;
                int jj = wl * 32 + b;
                float4 bb = sb[jj];
                bool ok = (j >= r) && (sl[jj] == la);
                if (ok) {
                    float xmin = fmaxf(a.x, bb.x), ymin = fmaxf(a.y, bb.y);
                    float xmax = fminf(a.z, bb.z), ymax = fminf(a.w, bb.w);
                    float inter = fmaxf(xmax - xmin, 0.f) * fmaxf(ymax - ymin, 0.f);
                    float iou = inter / fmaxf(aa + sa[jj] - inter, 1e-6f);
                    ok = iou > 0.3f;
                }
                if (ok) m |= (1u << b);
            }
            g_rows[r * WORDS + w] = m;
        }
        __syncthreads();
    }
}

// ---------------- kernel 4: compact candidate lists + degrees ----------------
__global__ void __launch_bounds__(1024) k_lists() {
    int gwarp = (blockIdx.x * blockDim.x + threadIdx.x) >> 5;
    int lane = threadIdx.x & 31;
    if (gwarp >= NBOX) return;
    const unsigned* row = g_rows + gwarp * WORDS;
    uint4 v4 = ((const uint4*)row)[lane];
    int w0 = gwarp >> 5;
    unsigned ws[4];
    ws[0] = (lane*4+0 >= w0) ? v4.x : 0u;
    ws[1] = (lane*4+1 >= w0) ? v4.y : 0u;
    ws[2] = (lane*4+2 >= w0) ? v4.z : 0u;
    ws[3] = (lane*4+3 >= w0) ? v4.w : 0u;
    int pc = __popc(ws[0]) + __popc(ws[1]) + __popc(ws[2]) + __popc(ws[3]);
    int incl = pc;
    for (int d = 1; d < 32; d <<= 1) {
        int n = __shfl_up_sync(0xffffffffu, incl, d);
        if (lane >= d) incl += n;
    }
    int total = __shfl_sync(0xffffffffu, incl, 31);
    int running = incl - pc;   // global bit rank; diag (bit i) is rank 0
#pragma unroll
    for (int q = 0; q < 4; q++) {
        unsigned v = ws[q];
        int base_j = (lane * 4 + q) * 32;
        while (v) {
            int b = __ffs(v) - 1; v &= v - 1;
            if (running > 0) {
                int idx = running - 1;
                if (idx < 31) g_list[gwarp * 32 + idx] = (unsigned short)(base_j + b);
            }
            running++;
        }
    }
    if (lane == 0) {
        int deg = total - 1;
        g_deg8[gwarp] = (unsigned char)(deg > 255 ? 255 : deg);
    }
}

// ---------------- kernel 5: per-label scans with deg0 run-skipping ----------------
__global__ void __launch_bounds__(128) k_scanA() {
    __shared__ unsigned sup[WORDS];
    __shared__ unsigned kp[WORDS];
    __shared__ unsigned sdeg0[WORDS];
    __shared__ unsigned sdeg_u[NBOX / 4];
    int t = threadIdx.x;
    int L = t >> 5;              // warp = label
    int lane = t & 31;
    for (int k = t; k < WORDS; k += 128) { sup[k] = g_sup0[k]; kp[k] = 0u; }
    for (int k = t; k < NBOX / 4; k += 128) sdeg_u[k] = ((const unsigned*)g_deg8)[k];
    __syncthreads();
    const unsigned char* sdeg = (const unsigned char*)sdeg_u;
    // build deg0 bitmap: thread t owns word t
    {
        unsigned m = 0;
#pragma unroll 8
        for (int b = 0; b < 32; b++)
            m |= (sdeg[t * 32 + b] == 0) ? (1u << b) : 0u;
        sdeg0[t] = m;
    }
    __syncthreads();
    const unsigned* labm = g_labmask + L * WORDS;

    int nt = 0;
    for (int w = 0; w < WORDS; w++) {
        unsigned lm = labm[w];
        if (!lm) continue;
        unsigned rem = ~sup[w] & lm;
        if (!rem) continue;
        unsigned d0 = sdeg0[w];
        unsigned kpw = 0;
        while (rem) {
            unsigned nond0 = rem & ~d0;
            if (!nond0) { kpw |= rem; break; }       // trailing deg0 run: all kept, free
            int b = __ffs(nond0) - 1;
            kpw |= rem & ~(0xfffffffeu << b);        // deg0 run before b + box b kept
            int i = w * 32 + b;
            // speculative prefetch of next candidate's list row
            unsigned nxt = nond0 & (0xfffffffeu << b);
            if (nxt)
                asm volatile("prefetch.global.L1 [%0];"
                             :: "l"(g_list + (w * 32 + __ffs(nxt) - 1) * 32));
            int deg = sdeg[i];
            if (deg <= 31) {
                bool val = lane < deg;
                int j = 0;
                if (val) {
                    j = (int)g_list[i * 32 + lane];
                    val = ((sup[j >> 5] >> (j & 31)) & 1u) == 0u;
                }
                unsigned m = __ballot_sync(0xffffffffu, val);
                int cnt = __popc(m) + 1;
                if (val) atomicOr(&sup[j >> 5], 1u << (j & 31));
                unsigned self = (val && ((j >> 5) == w)) ? (1u << (j & 31)) : 0u;
                unsigned cur = __reduce_or_sync(0xffffffffu, self);
                if (cnt > 1) {
                    int base = (L * NBOX + nt) * 24;
                    if (lane == 0) { g_tasks[base] = i; g_tasks[base + 1] = cnt; g_tasks[base + 2] = i; }
                    if (val) {
                        int rank = __popc(m & ((1u << lane) - 1u));
                        if (rank < 19) g_tasks[base + 3 + rank] = j;
                    }
                    nt++;
                }
                rem &= ~cur & (0xfffffffeu << b);
            } else {
                // exact bitmap fallback (rare)
                uint4 rv = ((const uint4*)(g_rows + (size_t)i * WORDS))[lane];
                int w0 = i >> 5;
                unsigned r0 = (4*lane+0 >= w0) ? rv.x : 0u;
                unsigned r1 = (4*lane+1 >= w0) ? rv.y : 0u;
                unsigned r2 = (4*lane+2 >= w0) ? rv.z : 0u;
                unsigned r3 = (4*lane+3 >= w0) ? rv.w : 0u;
                unsigned n0 = r0 & ~sup[4*lane+0], n1 = r1 & ~sup[4*lane+1];
                unsigned n2 = r2 & ~sup[4*lane+2], n3 = r3 & ~sup[4*lane+3];
                if (n0) atomicOr(&sup[4*lane+0], n0);
                if (n1) atomicOr(&sup[4*lane+1], n1);
                if (n2) atomicOr(&sup[4*lane+2], n2);
                if (n3) atomicOr(&sup[4*lane+3], n3);
                int pc = __popc(n0) + __popc(n1) + __popc(n2) + __popc(n3);
                int incl = pc;
                for (int d = 1; d < 32; d <<= 1) {
                    int v = __shfl_up_sync(0xffffffffu, incl, d);
                    if (lane >= d) incl += v;
                }
                int cnt = __shfl_sync(0xffffffffu, incl, 31);   // includes diag i
                if (cnt > 1) {
                    int base = (L * NBOX + nt) * 24;
                    if (lane == 0) { g_tasks[base] = i; g_tasks[base + 1] = cnt; }
                    int start = incl - pc;
                    unsigned nn[4] = { n0, n1, n2, n3 };
#pragma unroll
                    for (int q = 0; q < 4; q++) {
                        unsigned v = nn[q];
                        while (v && start < 20) {
                            int bb = __ffs(v) - 1; v &= v - 1;
                            g_tasks[base + 2 + start] = (4 * lane + q) * 32 + bb;
                            start++;
                        }
                    }
                    nt++;
                }
                int oq = w & 3;
                unsigned nown = (oq == 0) ? n0 : (oq == 1) ? n1 : (oq == 2) ? n2 : n3;
                unsigned cur = __shfl_sync(0xffffffffu, nown, w >> 2);
                rem &= ~cur & (0xfffffffeu << b);
            }
            __syncwarp();
        }
        if (lane == 0 && kpw) atomicOr(&kp[w], kpw);
    }
    if (lane == 0) g_ntv[L] = nt;
    __syncthreads();
    for (int k = t; k < WORDS; k += 128) g_keep[k] = kp[k];
}

// ---------------- kernel 6: parallel merge MLP + keep flags ----------------
__global__ void __launch_bounds__(128) k_merge(
    const float* __restrict__ w1, const float* __restrict__ b1,
    const float* __restrict__ w2, const float* __restrict__ b2,
    const float* __restrict__ w3, const float* __restrict__ b3,
    float* __restrict__ out) {
    __shared__ float ob[140];
    __shared__ float h1[112], h2[112];
    __shared__ float sw1[320], sw2[256], sw3[16], sb1v[16], sb2v[16];
    __shared__ float sb3v;
    int t = threadIdx.x;

    if (blockIdx.x < 32) {
        int s = blockIdx.x * 128 + t;
        out[NBOX * 11 + s] = ((g_keep[s >> 5] >> (s & 31)) & 1u) ? 1.0f : 0.0f;
    }

    for (int k = t; k < 320; k += 128) sw1[k] = w1[k];
    for (int k = t; k < 256; k += 128) sw2[k] = w2[k];
    if (t < 16) { sw3[t] = w3[t]; sb1v[t] = b1[t]; sb2v[t] = b2[t]; }
    if (t == 0) sb3v = b3[0];
    __syncthreads();

    for (int L = 0; L < NLAB; L++) {
        int nt = g_ntv[L];
        for (int task = blockIdx.x; task < nt; task += gridDim.x) {
            int base = (L * NBOX + task) * 24;
            int i = g_tasks[base];
            int cnt = g_tasks[base + 1];
            int mc = cnt < 20 ? cnt : 20;
            for (int e = t; e < 140; e += 128) {
                int m = e / 7, d = e - m * 7;
                ob[e] = (m < mc) ? g_boxes7[g_tasks[base + 2 + m] * 7 + d] : 0.f;
            }
            __syncthreads();
            if (t < 112) {
                int r = t >> 4, c = t & 15;
                float s = sb1v[c];
#pragma unroll
                for (int k = 0; k < MM; k++) s += ob[k * 7 + r] * sw1[k * HH + c];
                h1[t] = fmaxf(s, 0.f);
            }
            __syncthreads();
            if (t < 112) {
                int r = t >> 4, c = t & 15;
                float s = sb2v[c];
#pragma unroll
                for (int k = 0; k < HH; k++) s += h1[(r << 4) + k] * sw2[k * HH + c];
                h2[t] = fmaxf(s, 0.f);
            }
            __syncthreads();
            if (t < 7) {
                float s = sb3v;
#pragma unroll
                for (int k = 0; k < HH; k++) s += h2[(t << 4) + k] * sw3[k];
                if (t >= 3 && t < 6) s = fmaxf(s, 1e-5f);
                out[i * 9 + t] = s;
            }
            __syncthreads();
        }
    }
}

// ---------------- launch ----------------
extern "C" void kernel_launch(void* const* d_in, const int* in_sizes, int n_in,
                              void* d_out, int out_size) {
    const float* pb = (const float*)d_in[0];
    const float* ps = (const float*)d_in[1];
    const int*   pl = (const int*)  d_in[2];
    const float* w1 = (const float*)d_in[3];
    const float* b1 = (const float*)d_in[4];
    const float* w2 = (const float*)d_in[5];
    const float* b2 = (const float*)d_in[6];
    const float* w3 = (const float*)d_in[7];
    const float* b3 = (const float*)d_in[8];
    float* out = (float*)d_out;

    k_rank  <<<32, 128>>>(ps);
    k_prep  <<<32, 128>>>(pb, ps, pl, out);
    k_adj   <<<128, 1024>>>();
    k_lists <<<128, 1024>>>();
    k_scanA <<<1, 128>>>();
    k_merge <<<256, 128>>>(w1, b1, w2, b2, w3, b3, out);
}

// round 6
// speedup vs baseline: 7.7392x; 1.4310x over previous
#include <cuda_runtime.h>
#include <math.h>

#define NBOX 4096
#define WORDS 128   // NBOX/32
#define MM 20
#define HH 16
#define NLAB 4      // labels actually in {0,1,2}; 4th warp idles

// ---------------- device scratch ----------------
__device__ int            g_perm[NBOX];
__device__ float          g_boxes7[NBOX * 7];
__device__ float4         g_bev4[NBOX];
__device__ int            g_lab[NBOX];
__device__ unsigned int   g_sup0[WORDS];
__device__ unsigned int   g_labmask[NLAB * WORDS];
__device__ unsigned int   g_rows[NBOX * WORDS];        // adjacency bitmap (words >= w0 valid)
__device__ unsigned short g_list[NBOX * 32];           // compact lists (<=31 entries)
__device__ unsigned char  g_deg8[NBOX];
__device__ int            g_tasks[NLAB * NBOX * 24];   // per-label regions: [i, cnt, cand0..19, pad2]
__device__ int            g_ntv[NLAB];
__device__ unsigned int   g_keep[WORDS];

__device__ __forceinline__ unsigned sort_key(float sc) {
    float f = (sc > 0.2f) ? sc : __int_as_float(0xff800000); // -inf if invalid
    unsigned b = __float_as_uint(f);
    unsigned u = (b & 0x80000000u) ? ~b : (b | 0x80000000u);
    return ~u;   // ascending == score descending
}

// ---------------- kernel 1: O(N^2) rank sort ----------------
__global__ void k_rank(const float* __restrict__ scores) {
    __shared__ unsigned sk[NBOX];
    int t = threadIdx.x;
    for (int k = t; k < NBOX; k += blockDim.x) sk[k] = sort_key(scores[k]);
    __syncthreads();
    int i = blockIdx.x * blockDim.x + t;
    unsigned ki = sk[i];
    int rank = 0;
#pragma unroll 8
    for (int j = 0; j < NBOX; j++) {
        unsigned kj = sk[j];
        rank += (kj < ki) || (kj == ki && j < i);
    }
    g_perm[rank] = i;
}

// ---------------- kernel 2: gather, BEV, label masks, prefill outputs ----------------
__global__ void k_prep(const float* __restrict__ pb, const float* __restrict__ ps,
                       const int* __restrict__ pl, float* __restrict__ out) {
    int s = blockIdx.x * blockDim.x + threadIdx.x;
    int o = g_perm[s];
    float b0 = pb[o*9+0], b1 = pb[o*9+1], b2 = pb[o*9+2];
    float b3 = pb[o*9+3], b4 = pb[o*9+4], b5 = pb[o*9+5];
    float b6 = pb[o*9+6], b7 = pb[o*9+7], b8 = pb[o*9+8];
    g_boxes7[s*7+0] = b0; g_boxes7[s*7+1] = b1; g_boxes7[s*7+2] = b2;
    g_boxes7[s*7+3] = b3; g_boxes7[s*7+4] = b4; g_boxes7[s*7+5] = b5;
    g_boxes7[s*7+6] = b6;
    out[s*9+0] = b0; out[s*9+1] = b1; out[s*9+2] = b2;
    out[s*9+3] = b3; out[s*9+4] = b4; out[s*9+5] = b5;
    out[s*9+6] = b6; out[s*9+7] = b7; out[s*9+8] = b8;

    const float PI = 3.14159265358979323846f;
    float ang = b6 - floorf(b6 / PI + 0.5f) * PI;
    bool sw = fabsf(ang) >= 0.25f * PI;
    float dx = sw ? b4 : b3;
    float dy = sw ? b3 : b4;
    g_bev4[s] = make_float4(b0 - dx * 0.5f, b1 - dy * 0.5f, b0 + dx * 0.5f, b1 + dy * 0.5f);

    int lab = pl[o];
    g_lab[s] = lab;
    float sc = ps[o];
    out[NBOX*9  + s] = sc;
    out[NBOX*10 + s] = (float)lab;

    unsigned inval = __ballot_sync(0xffffffffu, !(sc > 0.2f));
    if ((threadIdx.x & 31) == 0) g_sup0[s >> 5] = inval;
#pragma unroll
    for (int L = 0; L < NLAB; L++) {
        unsigned lm = __ballot_sync(0xffffffffu, lab == L);
        if ((threadIdx.x & 31) == 0) g_labmask[L * WORDS + (s >> 5)] = lm;
    }
}

// ---------------- kernel 3: adjacency (label-masked ffs walk) + fused list compaction ----------------
__global__ void __launch_bounds__(1024) k_adj() {
    __shared__ float4 sb[1024];
    __shared__ float  sa[1024];
    __shared__ float4 rb[32];
    __shared__ int    rl[32];
    int t = threadIdx.x;
    int R = blockIdx.x * 32;
    if (t < 32) { rb[t] = g_bev4[R + t]; rl[t] = g_lab[R + t]; }
    __syncthreads();
    int rloc = t >> 5;
    int r = R + rloc;
    int wl = t & 31;
    float4 a = rb[rloc];
    int la = rl[rloc];
    float aa = (a.z - a.x) * (a.w - a.y);
    int w0 = blockIdx.x;               // r>>5 is identical for all rows in block
    int T0 = w0 >> 5;

    unsigned mw0 = 0, mw1 = 0, mw2 = 0, mw3 = 0;
#pragma unroll
    for (int T = 0; T < 4; T++) {
        if (T >= T0) {                 // uniform per block
            float4 bb0 = g_bev4[T * 1024 + t];
            sb[t] = bb0;
            sa[t] = (bb0.z - bb0.x) * (bb0.w - bb0.y);
            __syncthreads();
            int w = T * 32 + wl;
            unsigned m = 0;
            if (w >= w0) {
                unsigned cand = g_labmask[la * WORDS + w];
                if (w == w0) cand &= 0xffffffffu << (r & 31);
                while (cand) {
                    int b = __ffs(cand) - 1; cand &= cand - 1;
                    int jj = wl * 32 + b;
                    float4 bb = sb[jj];
                    float xmin = fmaxf(a.x, bb.x), ymin = fmaxf(a.y, bb.y);
                    float xmax = fminf(a.z, bb.z), ymax = fminf(a.w, bb.w);
                    float inter = fmaxf(xmax - xmin, 0.f) * fmaxf(ymax - ymin, 0.f);
                    float iou = inter / fmaxf(aa + sa[jj] - inter, 1e-6f);
                    if (iou > 0.3f) m |= 1u << b;
                }
                g_rows[r * WORDS + w] = m;   // fallback path still needs it
            }
            if (T == 0) mw0 = m; else if (T == 1) mw1 = m;
            else if (T == 2) mw2 = m; else mw3 = m;
            __syncthreads();
        }
    }

    // ---- fused compaction: warp rloc compacts row r from registers ----
    int running = 0;   // global bit rank; diag (bit r) is rank 0
#pragma unroll
    for (int T = 0; T < 4; T++) {
        unsigned v = (T == 0) ? mw0 : (T == 1) ? mw1 : (T == 2) ? mw2 : mw3;
        int pc = __popc(v);
        int incl = pc;
        for (int d = 1; d < 32; d <<= 1) {
            int n = __shfl_up_sync(0xffffffffu, incl, d);
            if (wl >= d) incl += n;
        }
        int start = running + incl - pc;
        int wword = T * 32 + wl;
        while (v) {
            int b = __ffs(v) - 1; v &= v - 1;
            if (start > 0 && start - 1 < 31)
                g_list[r * 32 + (start - 1)] = (unsigned short)(wword * 32 + b);
            start++;
        }
        running += __shfl_sync(0xffffffffu, incl, 31);
    }
    if (wl == 0) {
        int deg = running - 1;
        g_deg8[r] = (unsigned char)(deg > 255 ? 255 : deg);
    }
}

// ---------------- kernel 4: per-label scans with deg0 run-skipping ----------------
__global__ void __launch_bounds__(128) k_scanA() {
    __shared__ unsigned sup[WORDS];
    __shared__ unsigned kp[WORDS];
    __shared__ unsigned sdeg0[WORDS];
    __shared__ unsigned sdeg_u[NBOX / 4];
    int t = threadIdx.x;
    int L = t >> 5;              // warp = label
    int lane = t & 31;
    for (int k = t; k < WORDS; k += 128) { sup[k] = g_sup0[k]; kp[k] = 0u; }
    for (int k = t; k < NBOX / 4; k += 128) sdeg_u[k] = ((const unsigned*)g_deg8)[k];
    __syncthreads();
    const unsigned char* sdeg = (const unsigned char*)sdeg_u;
    {
        unsigned m = 0;
#pragma unroll 8
        for (int b = 0; b < 32; b++)
            m |= (sdeg[t * 32 + b] == 0) ? (1u << b) : 0u;
        sdeg0[t] = m;
    }
    __syncthreads();
    const unsigned* labm = g_labmask + L * WORDS;

    int nt = 0;
    for (int w = 0; w < WORDS; w++) {
        unsigned lm = labm[w];
        if (!lm) continue;
        unsigned rem = ~sup[w] & lm;
        if (!rem) continue;
        unsigned d0 = sdeg0[w];
        {   // prefetch first deg>=1 candidate's list row at word entry
            unsigned nd = rem & ~d0;
            if (nd)
                asm volatile("prefetch.global.L1 [%0];"
                             :: "l"(g_list + (w * 32 + __ffs(nd) - 1) * 32));
        }
        unsigned kpw = 0;
        while (rem) {
            unsigned nond0 = rem & ~d0;
            if (!nond0) { kpw |= rem; break; }       // trailing deg0 run: all kept, free
            int b = __ffs(nond0) - 1;
            kpw |= rem & ~(0xfffffffeu << b);        // deg0 run before b + box b kept
            int i = w * 32 + b;
            unsigned nxt = nond0 & (0xfffffffeu << b);
            if (nxt)
                asm volatile("prefetch.global.L1 [%0];"
                             :: "l"(g_list + (w * 32 + __ffs(nxt) - 1) * 32));
            int deg = sdeg[i];
            if (deg <= 31) {
                bool val = lane < deg;
                int j = 0;
                if (val) {
                    j = (int)g_list[i * 32 + lane];
                    val = ((sup[j >> 5] >> (j & 31)) & 1u) == 0u;
                }
                unsigned m = __ballot_sync(0xffffffffu, val);
                int cnt = __popc(m) + 1;
                if (val) atomicOr(&sup[j >> 5], 1u << (j & 31));
                unsigned self = (val && ((j >> 5) == w)) ? (1u << (j & 31)) : 0u;
                unsigned cur = __reduce_or_sync(0xffffffffu, self);
                if (cnt > 1) {
                    int base = (L * NBOX + nt) * 24;
                    if (lane == 0) { g_tasks[base] = i; g_tasks[base + 1] = cnt; g_tasks[base + 2] = i; }
                    if (val) {
                        int rank = __popc(m & ((1u << lane) - 1u));
                        if (rank < 19) g_tasks[base + 3 + rank] = j;
                    }
                    nt++;
                }
                rem &= ~cur & (0xfffffffeu << b);
            } else {
                // exact bitmap fallback (rare)
                uint4 rv = ((const uint4*)(g_rows + (size_t)i * WORDS))[lane];
                int w0 = i >> 5;
                unsigned r0 = (4*lane+0 >= w0) ? rv.x : 0u;
                unsigned r1 = (4*lane+1 >= w0) ? rv.y : 0u;
                unsigned r2 = (4*lane+2 >= w0) ? rv.z : 0u;
                unsigned r3 = (4*lane+3 >= w0) ? rv.w : 0u;
                unsigned n0 = r0 & ~sup[4*lane+0], n1 = r1 & ~sup[4*lane+1];
                unsigned n2 = r2 & ~sup[4*lane+2], n3 = r3 & ~sup[4*lane+3];
                if (n0) atomicOr(&sup[4*lane+0], n0);
                if (n1) atomicOr(&sup[4*lane+1], n1);
                if (n2) atomicOr(&sup[4*lane+2], n2);
                if (n3) atomicOr(&sup[4*lane+3], n3);
                int pc = __popc(n0) + __popc(n1) + __popc(n2) + __popc(n3);
                int incl = pc;
                for (int d = 1; d < 32; d <<= 1) {
                    int v = __shfl_up_sync(0xffffffffu, incl, d);
                    if (lane >= d) incl += v;
                }
                int cnt = __shfl_sync(0xffffffffu, incl, 31);   // includes diag i
                if (cnt > 1) {
                    int base = (L * NBOX + nt) * 24;
                    if (lane == 0) { g_tasks[base] = i; g_tasks[base + 1] = cnt; }
                    int start = incl - pc;
                    unsigned nn[4] = { n0, n1, n2, n3 };
#pragma unroll
                    for (int q = 0; q < 4; q++) {
                        unsigned v = nn[q];
                        while (v && start < 20) {
                            int bb = __ffs(v) - 1; v &= v - 1;
                            g_tasks[base + 2 + start] = (4 * lane + q) * 32 + bb;
                            start++;
                        }
                    }
                    nt++;
                }
                int oq = w & 3;
                unsigned nown = (oq == 0) ? n0 : (oq == 1) ? n1 : (oq == 2) ? n2 : n3;
                unsigned cur = __shfl_sync(0xffffffffu, nown, w >> 2);
                rem &= ~cur & (0xfffffffeu << b);
            }
            __syncwarp();
        }
        if (lane == 0 && kpw) atomicOr(&kp[w], kpw);
    }
    if (lane == 0) g_ntv[L] = nt;
    __syncthreads();
    for (int k = t; k < WORDS; k += 128) g_keep[k] = kp[k];
}

// ---------------- kernel 5: parallel merge MLP + keep flags ----------------
__global__ void __launch_bounds__(128) k_merge(
    const float* __restrict__ w1, const float* __restrict__ b1,
    const float* __restrict__ w2, const float* __restrict__ b2,
    const float* __restrict__ w3, const float* __restrict__ b3,
    float* __restrict__ out) {
    __shared__ float ob[140];
    __shared__ float h1[112], h2[112];
    __shared__ float sw1[320], sw2[256], sw3[16], sb1v[16], sb2v[16];
    __shared__ float sb3v;
    int t = threadIdx.x;

    if (blockIdx.x < 32) {
        int s = blockIdx.x * 128 + t;
        out[NBOX * 11 + s] = ((g_keep[s >> 5] >> (s & 31)) & 1u) ? 1.0f : 0.0f;
    }

    for (int k = t; k < 320; k += 128) sw1[k] = w1[k];
    for (int k = t; k < 256; k += 128) sw2[k] = w2[k];
    if (t < 16) { sw3[t] = w3[t]; sb1v[t] = b1[t]; sb2v[t] = b2[t]; }
    if (t == 0) sb3v = b3[0];
    __syncthreads();

    for (int L = 0; L < NLAB; L++) {
        int nt = g_ntv[L];
        for (int task = blockIdx.x; task < nt; task += gridDim.x) {
            int base = (L * NBOX + task) * 24;
            int i = g_tasks[base];
            int cnt = g_tasks[base + 1];
            int mc = cnt < 20 ? cnt : 20;
            for (int e = t; e < 140; e += 128) {
                int m = e / 7, d = e - m * 7;
                ob[e] = (m < mc) ? g_boxes7[g_tasks[base + 2 + m] * 7 + d] : 0.f;
            }
            __syncthreads();
            if (t < 112) {
                int r = t >> 4, c = t & 15;
                float s = sb1v[c];
#pragma unroll
                for (int k = 0; k < MM; k++) s += ob[k * 7 + r] * sw1[k * HH + c];
                h1[t] = fmaxf(s, 0.f);
            }
            __syncthreads();
            if (t < 112) {
                int r = t >> 4, c = t & 15;
                float s = sb2v[c];
#pragma unroll
                for (int k = 0; k < HH; k++) s += h1[(r << 4) + k] * sw2[k * HH + c];
                h2[t] = fmaxf(s, 0.f);
            }
            __syncthreads();
            if (t < 7) {
                float s = sb3v;
#pragma unroll
                for (int k = 0; k < HH; k++) s += h2[(t << 4) + k] * sw3[k];
                if (t >= 3 && t < 6) s = fmaxf(s, 1e-5f);
                out[i * 9 + t] = s;
            }
            __syncthreads();
        }
    }
}

// ---------------- launch ----------------
extern "C" void kernel_launch(void* const* d_in, const int* in_sizes, int n_in,
                              void* d_out, int out_size) {
    const float* pb = (const float*)d_in[0];
    const float* ps = (const float*)d_in[1];
    const int*   pl = (const int*)  d_in[2];
    const float* w1 = (const float*)d_in[3];
    const float* b1 = (const float*)d_in[4];
    const float* w2 = (const float*)d_in[5];
    const float* b2 = (const float*)d_in[6];
    const float* w3 = (const float*)d_in[7];
    const float* b3 = (const float*)d_in[8];
    float* out = (float*)d_out;

    k_rank  <<<32, 128>>>(ps);
    k_prep  <<<32, 128>>>(pb, ps, pl, out);
    k_adj   <<<128, 1024>>>();
    k_scanA <<<1, 128>>>();
    k_merge <<<256, 128>>>(w1, b1, w2, b2, w3, b3, out);
}

// round 7
// speedup vs baseline: 10.5641x; 1.3650x over previous
#include <cuda_runtime.h>
#include <math.h>

#define NBOX 4096
#define WORDS 128   // NBOX/32
#define MM 20
#define HH 16
#define NLAB 4      // labels actually in {0,1,2}; 4th warp idles
#define POOLSM 8192 // smem pool window (entries)

// ---------------- device scratch ----------------
__device__ int            g_perm[NBOX];
__device__ float          g_boxes7[NBOX * 7];
__device__ float4         g_bev4[NBOX];
__device__ int            g_lab[NBOX];
__device__ unsigned int   g_sup0[WORDS];
__device__ unsigned int   g_labmask[NLAB * WORDS];
__device__ unsigned int   g_rows[NBOX * WORDS];        // only deg>31 rows valid
__device__ unsigned short g_pool[NBOX * 31];           // compacted neighbor lists
__device__ unsigned int   g_ofsdeg[NBOX];              // ofs(24) | min(deg,255)(8)
__device__ unsigned int   g_poolcnt;
__device__ int            g_tasks[NLAB * NBOX * 24];   // per-label regions
__device__ int            g_ntv[NLAB];
__device__ unsigned int   g_keep[WORDS];

__device__ __forceinline__ unsigned sort_key(float sc) {
    float f = (sc > 0.2f) ? sc : __int_as_float(0xff800000);
    unsigned b = __float_as_uint(f);
    unsigned u = (b & 0x80000000u) ? ~b : (b | 0x80000000u);
    return ~u;   // ascending == score descending
}

// ---------------- kernel 1: O(N^2) rank sort ----------------
__global__ void k_rank(const float* __restrict__ scores) {
    __shared__ unsigned sk[NBOX];
    int t = threadIdx.x;
    if (blockIdx.x == 0 && t == 0) g_poolcnt = 0;   // reset pool each launch
    for (int k = t; k < NBOX; k += blockDim.x) sk[k] = sort_key(scores[k]);
    __syncthreads();
    int i = blockIdx.x * blockDim.x + t;
    unsigned ki = sk[i];
    int rank = 0;
    const uint4* sk4 = (const uint4*)sk;
#pragma unroll 4
    for (int j4 = 0; j4 < NBOX / 4; j4++) {
        uint4 v = sk4[j4];
        int j = j4 * 4;
        rank += (v.x < ki) || (v.x == ki && j + 0 < i);
        rank += (v.y < ki) || (v.y == ki && j + 1 < i);
        rank += (v.z < ki) || (v.z == ki && j + 2 < i);
        rank += (v.w < ki) || (v.w == ki && j + 3 < i);
    }
    g_perm[rank] = i;
}

// ---------------- kernel 2: gather, BEV, label masks, prefill outputs ----------------
__global__ void k_prep(const float* __restrict__ pb, const float* __restrict__ ps,
                       const int* __restrict__ pl, float* __restrict__ out) {
    int s = blockIdx.x * blockDim.x + threadIdx.x;
    int o = g_perm[s];
    float b0 = pb[o*9+0], b1 = pb[o*9+1], b2 = pb[o*9+2];
    float b3 = pb[o*9+3], b4 = pb[o*9+4], b5 = pb[o*9+5];
    float b6 = pb[o*9+6], b7 = pb[o*9+7], b8 = pb[o*9+8];
    g_boxes7[s*7+0] = b0; g_boxes7[s*7+1] = b1; g_boxes7[s*7+2] = b2;
    g_boxes7[s*7+3] = b3; g_boxes7[s*7+4] = b4; g_boxes7[s*7+5] = b5;
    g_boxes7[s*7+6] = b6;
    out[s*9+0] = b0; out[s*9+1] = b1; out[s*9+2] = b2;
    out[s*9+3] = b3; out[s*9+4] = b4; out[s*9+5] = b5;
    out[s*9+6] = b6; out[s*9+7] = b7; out[s*9+8] = b8;

    const float PI = 3.14159265358979323846f;
    float ang = b6 - floorf(b6 / PI + 0.5f) * PI;
    bool sw = fabsf(ang) >= 0.25f * PI;
    float dx = sw ? b4 : b3;
    float dy = sw ? b3 : b4;
    g_bev4[s] = make_float4(b0 - dx * 0.5f, b1 - dy * 0.5f, b0 + dx * 0.5f, b1 + dy * 0.5f);

    int lab = pl[o];
    g_lab[s] = lab;
    float sc = ps[o];
    out[NBOX*9  + s] = sc;
    out[NBOX*10 + s] = (float)lab;

    unsigned inval = __ballot_sync(0xffffffffu, !(sc > 0.2f));
    if ((threadIdx.x & 31) == 0) g_sup0[s >> 5] = inval;
#pragma unroll
    for (int L = 0; L < NLAB; L++) {
        unsigned lm = __ballot_sync(0xffffffffu, lab == L);
        if ((threadIdx.x & 31) == 0) g_labmask[L * WORDS + (s >> 5)] = lm;
    }
}

// ---------------- kernel 3: adjacency + pool compaction (no g_rows unless deg>31) ----------------
__global__ void __launch_bounds__(1024) k_adj() {
    __shared__ float4 sb[1024];
    __shared__ float  sa[1024];
    __shared__ float4 rb[32];
    __shared__ int    rl[32];
    int t = threadIdx.x;
    int R = blockIdx.x * 32;
    if (t < 32) { rb[t] = g_bev4[R + t]; rl[t] = g_lab[R + t]; }
    __syncthreads();
    int rloc = t >> 5;
    int r = R + rloc;
    int wl = t & 31;
    float4 a = rb[rloc];
    int la = rl[rloc];
    float aa = (a.z - a.x) * (a.w - a.y);
    int w0 = blockIdx.x;
    int T0 = w0 >> 5;

    unsigned mw[4] = {0, 0, 0, 0};
#pragma unroll
    for (int T = 0; T < 4; T++) {
        if (T >= T0) {
            float4 bb0 = g_bev4[T * 1024 + t];
            sb[t] = bb0;
            sa[t] = (bb0.z - bb0.x) * (bb0.w - bb0.y);
            __syncthreads();
            int w = T * 32 + wl;
            unsigned m = 0;
            if (w >= w0) {
                unsigned cand = g_labmask[la * WORDS + w];
                if (w == w0) cand &= 0xffffffffu << (r & 31);
                while (cand) {
                    int b = __ffs(cand) - 1; cand &= cand - 1;
                    int jj = wl * 32 + b;
                    float4 bb = sb[jj];
                    float xmin = fmaxf(a.x, bb.x), ymin = fmaxf(a.y, bb.y);
                    float xmax = fminf(a.z, bb.z), ymax = fminf(a.w, bb.w);
                    float inter = fmaxf(xmax - xmin, 0.f) * fmaxf(ymax - ymin, 0.f);
                    float iou = inter / fmaxf(aa + sa[jj] - inter, 1e-6f);
                    if (iou > 0.3f) m |= 1u << b;
                }
            }
            mw[T] = m;
            __syncthreads();
        }
    }

    // ---- prefix scans: exclusive lane offsets + tile bases ----
    int excl[4], tbase[4];
    int running = 0;
#pragma unroll
    for (int T = 0; T < 4; T++) {
        int pc = __popc(mw[T]);
        int incl = pc;
        for (int d = 1; d < 32; d <<= 1) {
            int n = __shfl_up_sync(0xffffffffu, incl, d);
            if (wl >= d) incl += n;
        }
        excl[T] = incl - pc;
        tbase[T] = running;
        running += __shfl_sync(0xffffffffu, incl, 31);
    }
    int deg = running - 1;            // diag always set
    int cap = deg < 31 ? deg : 31;

    unsigned base = 0;
    if (wl == 0 && deg > 0) base = atomicAdd(&g_poolcnt, (unsigned)cap);
    base = __shfl_sync(0xffffffffu, base, 0);

#pragma unroll
    for (int T = 0; T < 4; T++) {
        unsigned v = mw[T];
        int rank0 = tbase[T] + excl[T];   // global bit rank; diag is rank 0
        int wword = T * 32 + wl;
        while (v) {
            int b = __ffs(v) - 1; v &= v - 1;
            if (rank0 > 0 && rank0 - 1 < 31)
                g_pool[base + rank0 - 1] = (unsigned short)(wword * 32 + b);
            rank0++;
        }
    }
    if (wl == 0)
        g_ofsdeg[r] = base | ((unsigned)(deg > 255 ? 255 : deg) << 24);

    if (deg > 31) {   // rare: dump full row for the bitmap fallback
        g_rows[r * WORDS +       wl] = mw[0];
        g_rows[r * WORDS +  32 + wl] = mw[1];
        g_rows[r * WORDS +  64 + wl] = mw[2];
        g_rows[r * WORDS +  96 + wl] = mw[3];
    }
}

// ---------------- kernel 4: per-label scans — all hot loads in smem ----------------
__global__ void __launch_bounds__(128) k_scanA() {
    __shared__ unsigned sup[WORDS];
    __shared__ unsigned kp[WORDS];
    __shared__ unsigned sdeg0[WORDS];
    __shared__ unsigned slabm[NLAB * WORDS];
    __shared__ unsigned sod[NBOX];              // 16 KB packed ofs|deg
    __shared__ unsigned short spool[POOLSM];    // 16 KB pool window
    int t = threadIdx.x;
    int L = t >> 5;
    int lane = t & 31;
    for (int k = t; k < WORDS; k += 128) { sup[k] = g_sup0[k]; kp[k] = 0u; }
    for (int k = t; k < NLAB * WORDS; k += 128) slabm[k] = g_labmask[k];
    for (int k = t; k < NBOX; k += 128) sod[k] = g_ofsdeg[k];
    for (int k = t; k < POOLSM / 2; k += 128)
        ((unsigned*)spool)[k] = ((const unsigned*)g_pool)[k];
    __syncthreads();
    {   // deg0 bitmap: thread t owns word t
        unsigned m = 0;
#pragma unroll 8
        for (int b = 0; b < 32; b++)
            m |= ((sod[t * 32 + b] >> 24) == 0u) ? (1u << b) : 0u;
        sdeg0[t] = m;
    }
    __syncthreads();
    const unsigned* labm = slabm + L * WORDS;

    int nt = 0;
    for (int w = 0; w < WORDS; w++) {
        unsigned lm = labm[w];
        if (!lm) continue;
        unsigned rem = ~sup[w] & lm;
        if (!rem) continue;
        unsigned d0 = sdeg0[w];
        unsigned kpw = 0;
        while (rem) {
            unsigned nond0 = rem & ~d0;
            if (!nond0) { kpw |= rem; break; }
            int b = __ffs(nond0) - 1;
            kpw |= rem & ~(0xfffffffeu << b);
            int i = w * 32 + b;
            unsigned od = sod[i];
            int deg = od >> 24;
            int ofs = od & 0xffffff;
            if (deg <= 31) {
                bool val = lane < deg;
                int j = 0;
                if (val) {
                    int p = ofs + lane;
                    j = (p < POOLSM) ? (int)spool[p] : (int)g_pool[p];
                    val = ((sup[j >> 5] >> (j & 31)) & 1u) == 0u;
                }
                unsigned m = __ballot_sync(0xffffffffu, val);
                int cnt = __popc(m) + 1;
                if (val) atomicOr(&sup[j >> 5], 1u << (j & 31));
                unsigned self = (val && ((j >> 5) == w)) ? (1u << (j & 31)) : 0u;
                unsigned cur = __reduce_or_sync(0xffffffffu, self);
                if (cnt > 1) {
                    int base = (L * NBOX + nt) * 24;
                    if (lane == 0) { g_tasks[base] = i; g_tasks[base + 1] = cnt; g_tasks[base + 2] = i; }
                    if (val) {
                        int rank = __popc(m & ((1u << lane) - 1u));
                        if (rank < 19) g_tasks[base + 3 + rank] = j;
                    }
                    nt++;
                }
                rem &= ~cur & (0xfffffffeu << b);
            } else {
                // exact bitmap fallback (rare; g_rows dumped for deg>31)
                uint4 rv = ((const uint4*)(g_rows + (size_t)i * WORDS))[lane];
                int ww0 = i >> 5;
                unsigned r0 = (4*lane+0 >= ww0) ? rv.x : 0u;
                unsigned r1 = (4*lane+1 >= ww0) ? rv.y : 0u;
                unsigned r2 = (4*lane+2 >= ww0) ? rv.z : 0u;
                unsigned r3 = (4*lane+3 >= ww0) ? rv.w : 0u;
                unsigned n0 = r0 & ~sup[4*lane+0], n1 = r1 & ~sup[4*lane+1];
                unsigned n2 = r2 & ~sup[4*lane+2], n3 = r3 & ~sup[4*lane+3];
                if (n0) atomicOr(&sup[4*lane+0], n0);
                if (n1) atomicOr(&sup[4*lane+1], n1);
                if (n2) atomicOr(&sup[4*lane+2], n2);
                if (n3) atomicOr(&sup[4*lane+3], n3);
                int pc = __popc(n0) + __popc(n1) + __popc(n2) + __popc(n3);
                int incl = pc;
                for (int d = 1; d < 32; d <<= 1) {
                    int v = __shfl_up_sync(0xffffffffu, incl, d);
                    if (lane >= d) incl += v;
                }
                int cnt = __shfl_sync(0xffffffffu, incl, 31);
                if (cnt > 1) {
                    int base = (L * NBOX + nt) * 24;
                    if (lane == 0) { g_tasks[base] = i; g_tasks[base + 1] = cnt; }
                    int start = incl - pc;
                    unsigned nn[4] = { n0, n1, n2, n3 };
#pragma unroll
                    for (int q = 0; q < 4; q++) {
                        unsigned v = nn[q];
                        while (v && start < 20) {
                            int bb = __ffs(v) - 1; v &= v - 1;
                            g_tasks[base + 2 + start] = (4 * lane + q) * 32 + bb;
                            start++;
                        }
                    }
                    nt++;
                }
                int oq = w & 3;
                unsigned nown = (oq == 0) ? n0 : (oq == 1) ? n1 : (oq == 2) ? n2 : n3;
                unsigned cur = __shfl_sync(0xffffffffu, nown, w >> 2);
                rem &= ~cur & (0xfffffffeu << b);
            }
            __syncwarp();
        }
        if (lane == 0 && kpw) atomicOr(&kp[w], kpw);
    }
    if (lane == 0) g_ntv[L] = nt;
    __syncthreads();
    for (int k = t; k < WORDS; k += 128) g_keep[k] = kp[k];
}

// ---------------- kernel 5: parallel merge MLP + keep flags ----------------
__global__ void __launch_bounds__(128) k_merge(
    const float* __restrict__ w1, const float* __restrict__ b1,
    const float* __restrict__ w2, const float* __restrict__ b2,
    const float* __restrict__ w3, const float* __restrict__ b3,
    float* __restrict__ out) {
    __shared__ float ob[140];
    __shared__ float h1[112], h2[112];
    __shared__ float sw1[320], sw2[256], sw3[16], sb1v[16], sb2v[16];
    __shared__ float sb3v;
    int t = threadIdx.x;

    if (blockIdx.x < 32) {
        int s = blockIdx.x * 128 + t;
        out[NBOX * 11 + s] = ((g_keep[s >> 5] >> (s & 31)) & 1u) ? 1.0f : 0.0f;
    }

    for (int k = t; k < 320; k += 128) sw1[k] = w1[k];
    for (int k = t; k < 256; k += 128) sw2[k] = w2[k];
    if (t < 16) { sw3[t] = w3[t]; sb1v[t] = b1[t]; sb2v[t] = b2[t]; }
    if (t == 0) sb3v = b3[0];
    __syncthreads();

    for (int L = 0; L < NLAB; L++) {
        int nt = g_ntv[L];
        for (int task = blockIdx.x; task < nt; task += gridDim.x) {
            int base = (L * NBOX + task) * 24;
            int i = g_tasks[base];
            int cnt = g_tasks[base + 1];
            int mc = cnt < 20 ? cnt : 20;
            for (int e = t; e < 140; e += 128) {
                int m = e / 7, d = e - m * 7;
                ob[e] = (m < mc) ? g_boxes7[g_tasks[base + 2 + m] * 7 + d] : 0.f;
            }
            __syncthreads();
            if (t < 112) {
                int r = t >> 4, c = t & 15;
                float s = sb1v[c];
#pragma unroll
                for (int k = 0; k < MM; k++) s += ob[k * 7 + r] * sw1[k * HH + c];
                h1[t] = fmaxf(s, 0.f);
            }
            __syncthreads();
            if (t < 112) {
                int r = t >> 4, c = t & 15;
                float s = sb2v[c];
#pragma unroll
                for (int k = 0; k < HH; k++) s += h1[(r << 4) + k] * sw2[k * HH + c];
                h2[t] = fmaxf(s, 0.f);
            }
            __syncthreads();
            if (t < 7) {
                float s = sb3v;
#pragma unroll
                for (int k = 0; k < HH; k++) s += h2[(t << 4) + k] * sw3[k];
                if (t >= 3 && t < 6) s = fmaxf(s, 1e-5f);
                out[i * 9 + t] = s;
            }
            __syncthreads();
        }
    }
}

// ---------------- launch ----------------
extern "C" void kernel_launch(void* const* d_in, const int* in_sizes, int n_in,
                              void* d_out, int out_size) {
    const float* pb = (const float*)d_in[0];
    const float* ps = (const float*)d_in[1];
    const int*   pl = (const int*)  d_in[2];
    const float* w1 = (const float*)d_in[3];
    const float* b1 = (const float*)d_in[4];
    const float* w2 = (const float*)d_in[5];
    const float* b2 = (const float*)d_in[6];
    const float* w3 = (const float*)d_in[7];
    const float* b3 = (const float*)d_in[8];
    float* out = (float*)d_out;

    k_rank  <<<32, 128>>>(ps);
    k_prep  <<<32, 128>>>(pb, ps, pl, out);
    k_adj   <<<128, 1024>>>();
    k_scanA <<<1, 128>>>();
    k_merge <<<256, 128>>>(w1, b1, w2, b2, w3, b3, out);
}